// round 16
// baseline (speedup 1.0000x reference)
#include <cuda_runtime.h>
#include <cuda_bf16.h>
#include <mma.h>
#include <cstdint>

using namespace nvcuda;

// ---------------- problem constants ----------------
#define L_SEQ 2048
#define DM    1024
#define DI    2048
#define NX    96      // dt_rank + 2*d_state
#define RK    64      // dt_rank
#define NS    16      // d_state

// ---------------- device scratch (static globals, no allocs) ----------------
__device__ __align__(128) __nv_bfloat16 g_xn  [(size_t)L_SEQ * DM];     // normalized input  [l][dm]
__device__ __align__(128) __nv_bfloat16 g_Win [(size_t)2 * DI * DM];    // W_in bf16 [4096][1024]
__device__ __align__(128) __nv_bfloat16 g_Wxp [(size_t)NX * DI];        // W_xproj bf16 [96][2048]
__device__ __align__(128) __nv_bfloat16 g_Wout[(size_t)DM * DI];        // W_out bf16 [1024][2048]
__device__ __align__(128) float         g_xzT [(size_t)2 * DI * L_SEQ]; // in_proj out, [e][l]
__device__ __align__(128) float         g_xsT [(size_t)DI * L_SEQ];     // conv+silu fp32 [d][l]
__device__ __align__(128) __nv_bfloat16 g_xsTb[(size_t)DI * L_SEQ];     // conv+silu bf16 [d][l]
__device__ __align__(128) float         g_dbc [(size_t)L_SEQ * NX];     // x_proj out [l][96]
__device__ __align__(128) float         g_BC  [(size_t)L_SEQ * 32];     // [l][0..15]=B, [16..31]=C
__device__ __align__(128) float         g_deltaT[(size_t)DI * L_SEQ];   // softplus delta [d][l]
__device__ __align__(128) float         g_gT  [(size_t)DI * L_SEQ];     // silu(res) [d][l]
__device__ __align__(128) __nv_bfloat16 g_ygT [(size_t)DI * L_SEQ];     // gated scan out bf16 [d][l]

// ---------------- helpers ----------------
__device__ __forceinline__ float silu_f(float z) {
    return z / (1.f + __expf(-z));
}
__device__ __forceinline__ float softplus_f(float z) {
    return (z > 20.f) ? z : log1pf(__expf(z));
}
__device__ __forceinline__ float f4_get(const float4& v, int j) {
    switch (j) { case 0: return v.x; case 1: return v.y; case 2: return v.z; default: return v.w; }
}

// ---------------- fp32 -> bf16 weight conversion ----------------
__global__ void f2bf_kernel(const float* __restrict__ src, int which, int n2) {
    __nv_bfloat16* dst = (which == 0) ? g_Win : (which == 1) ? g_Wxp : g_Wout;
    int stride = gridDim.x * blockDim.x;
    for (int i = blockIdx.x * blockDim.x + threadIdx.x; i < n2; i += stride) {
        float2 v = ((const float2*)src)[i];
        ((__nv_bfloat162*)dst)[i] = __floats2bfloat162_rn(v.x, v.y);
    }
}

// ---------------- RMSNorm: x[l][1024] fp32 -> g_xn bf16 ----------------
__global__ void rmsnorm_kernel(const float* __restrict__ x, const float* __restrict__ nw) {
    const int l = blockIdx.x;
    const int tid = threadIdx.x;  // 256 threads x 4 elems
    float4 v = ((const float4*)(x + (size_t)l * DM))[tid];
    float ss = v.x * v.x + v.y * v.y + v.z * v.z + v.w * v.w;
    #pragma unroll
    for (int o = 16; o > 0; o >>= 1) ss += __shfl_xor_sync(0xffffffffu, ss, o);
    __shared__ float wsum[8];
    if ((tid & 31) == 0) wsum[tid >> 5] = ss;
    __syncthreads();
    float tot = 0.f;
    #pragma unroll
    for (int w = 0; w < 8; w++) tot += wsum[w];
    float r = rsqrtf(tot * (1.0f / DM) + 1e-5f);
    float4 w4 = ((const float4*)nw)[tid];
    __nv_bfloat162* op = (__nv_bfloat162*)(g_xn + (size_t)l * DM);
    op[tid * 2 + 0] = __floats2bfloat162_rn(v.x * r * w4.x, v.y * r * w4.y);
    op[tid * 2 + 1] = __floats2bfloat162_rn(v.z * r * w4.z, v.w * r * w4.w);
}

// ---------------- bf16 wmma GEMM ----------------
// C[m,n] (fp32, row-major, ld=N) = sum_k A(m,k)*B(k,n)
//   A_KMAJOR=true :  A(m,k) = Ag[m*K + k]
//   A_KMAJOR=false:  A(m,k) = Ag[k*M + m]
//   B(k,n) = Bg[n*K + k]   (always)
// Requires M % 128 == 0, K % 32 == 0, N % 16 == 0 (N may be non-multiple of 64).
#define GBM 128
#define GBN 64
#define GBK 32

template<bool A_KMAJOR>
__global__ void gemm_kernel(const __nv_bfloat16* __restrict__ Ag,
                            const __nv_bfloat16* __restrict__ Bg,
                            float* __restrict__ C,
                            int M, int N, int K) {
    __shared__ __align__(128) __nv_bfloat16 As[GBM][GBK + 8];  // ld=40
    __shared__ __align__(128) __nv_bfloat16 Bs[GBK][GBN + 8];  // ld=72

    const int tid = threadIdx.x;              // 256 threads
    const int warpId = tid >> 5;
    const int wm = warpId & 3;                // 4 warp rows of 32
    const int wn = warpId >> 2;               // 2 warp cols of 32
    const int m0 = blockIdx.y * GBM;
    const int n0 = blockIdx.x * GBN;

    wmma::fragment<wmma::accumulator, 16, 16, 16, float> acc[2][2];
    #pragma unroll
    for (int i = 0; i < 2; i++)
        #pragma unroll
        for (int j = 0; j < 2; j++)
            wmma::fill_fragment(acc[i][j], 0.0f);

    for (int k0 = 0; k0 < K; k0 += GBK) {
        // ---- load A tile ----
        if (A_KMAJOR) {
            #pragma unroll
            for (int it = 0; it < 4; it++) {
                int idx = tid + it * 256;          // 1024 uint2 units
                int mm = idx >> 3, kq = idx & 7;
                uint2 v = *(const uint2*)(Ag + (size_t)(m0 + mm) * K + k0 + kq * 4);
                *(uint2*)(&As[mm][kq * 4]) = v;
            }
        } else {
            #pragma unroll
            for (int it = 0; it < 4; it++) {
                int idx = tid + it * 256;
                int kk = idx >> 5, mq = idx & 31;
                uint2 v = *(const uint2*)(Ag + (size_t)(k0 + kk) * M + m0 + mq * 4);
                __nv_bfloat16 e[4];
                *(uint2*)e = v;
                #pragma unroll
                for (int j = 0; j < 4; j++) As[mq * 4 + j][kk] = e[j];
            }
        }
        // ---- load B tile ----
        #pragma unroll
        for (int it = 0; it < 2; it++) {
            int idx = tid + it * 256;              // 512 uint2 units
            int nn = idx >> 3, kq = idx & 7;
            uint2 v = make_uint2(0u, 0u);
            if (n0 + nn < N)
                v = *(const uint2*)(Bg + (size_t)(n0 + nn) * K + k0 + kq * 4);
            __nv_bfloat16 e[4];
            *(uint2*)e = v;
            #pragma unroll
            for (int j = 0; j < 4; j++) Bs[kq * 4 + j][nn] = e[j];
        }
        __syncthreads();

        #pragma unroll
        for (int kk = 0; kk < GBK; kk += 16) {
            wmma::fragment<wmma::matrix_a, 16, 16, 16, __nv_bfloat16, wmma::row_major> a0, a1;
            wmma::fragment<wmma::matrix_b, 16, 16, 16, __nv_bfloat16, wmma::row_major> b0, b1;
            wmma::load_matrix_sync(a0, &As[wm * 32 + 0][kk], GBK + 8);
            wmma::load_matrix_sync(a1, &As[wm * 32 + 16][kk], GBK + 8);
            wmma::load_matrix_sync(b0, &Bs[kk][wn * 32 + 0], GBN + 8);
            wmma::load_matrix_sync(b1, &Bs[kk][wn * 32 + 16], GBN + 8);
            wmma::mma_sync(acc[0][0], a0, b0, acc[0][0]);
            wmma::mma_sync(acc[0][1], a0, b1, acc[0][1]);
            wmma::mma_sync(acc[1][0], a1, b0, acc[1][0]);
            wmma::mma_sync(acc[1][1], a1, b1, acc[1][1]);
        }
        __syncthreads();
    }

    #pragma unroll
    for (int i = 0; i < 2; i++) {
        #pragma unroll
        for (int j = 0; j < 2; j++) {
            int row = m0 + wm * 32 + i * 16;
            int col = n0 + wn * 32 + j * 16;
            if (col < N)
                wmma::store_matrix_sync(&C[(size_t)row * N + col], acc[i][j], N, wmma::mem_row_major);
        }
    }
}

// ---------------- depthwise causal conv1d + silu ----------------
__global__ void conv_kernel(const float* __restrict__ conv_w, const float* __restrict__ conv_b) {
    const int d = blockIdx.x;
    __shared__ float row[L_SEQ + 4];
    const int tid = threadIdx.x;  // 256
    if (tid < 4) row[tid] = 0.f;
    const float* src = g_xzT + (size_t)d * L_SEQ;
    float4* dst4 = (float4*)(row + 4);
    for (int i = tid; i < L_SEQ / 4; i += 256) dst4[i] = ((const float4*)src)[i];
    __syncthreads();
    const float w0 = conv_w[d * 4 + 0], w1 = conv_w[d * 4 + 1];
    const float w2 = conv_w[d * 4 + 2], w3 = conv_w[d * 4 + 3];
    const float b = conv_b[d];
    float* outF = g_xsT + (size_t)d * L_SEQ;
    __nv_bfloat162* outB = (__nv_bfloat162*)(g_xsTb + (size_t)d * L_SEQ);
    for (int i = tid; i < L_SEQ / 4; i += 256) {
        int l = i * 4;
        float o[4];
        #pragma unroll
        for (int j = 0; j < 4; j++) {
            int ll = l + j;
            float s = row[ll + 1] * w0 + row[ll + 2] * w1 + row[ll + 3] * w2 + row[ll + 4] * w3 + b;
            o[j] = silu_f(s);
        }
        ((float4*)outF)[i] = make_float4(o[0], o[1], o[2], o[3]);
        outB[i * 2 + 0] = __floats2bfloat162_rn(o[0], o[1]);
        outB[i * 2 + 1] = __floats2bfloat162_rn(o[2], o[3]);
    }
}

// ---------------- gate: g = silu(res) ----------------
__global__ void gate_kernel() {
    size_t i = (size_t)blockIdx.x * blockDim.x + threadIdx.x;  // over DI*L/4 float4
    const float4* src = (const float4*)(g_xzT + (size_t)DI * L_SEQ);
    float4 v = src[i];
    ((float4*)g_gT)[i] = make_float4(silu_f(v.x), silu_f(v.y), silu_f(v.z), silu_f(v.w));
}

// ---------------- BC repack: [l][96] cols 64..95 -> [l][32] ----------------
__global__ void bc_repack_kernel() {
    int idx = blockIdx.x * blockDim.x + threadIdx.x;  // L*32
    int l = idx >> 5, j = idx & 31;
    g_BC[idx] = g_dbc[(size_t)l * NX + RK + j];
}

// ---------------- delta projection + softplus ----------------
// deltaT[d][l] = softplus(b_dt[d] + sum_r W_dt[d][r] * dbc[l][r])
__global__ void delta_kernel(const float* __restrict__ W_dt, const float* __restrict__ b_dt) {
    __shared__ float dts[64][65];
    __shared__ float Ws [64][65];
    const int l0 = blockIdx.x * 64;
    const int d0 = blockIdx.y * 64;
    const int tid = threadIdx.x;  // 256
    for (int i = tid; i < 64 * 64; i += 256) {
        int ll = i >> 6, r = i & 63;
        dts[ll][r] = g_dbc[(size_t)(l0 + ll) * NX + r];
    }
    for (int i = tid; i < 64 * 64; i += 256) {
        int dd = i >> 6, r = i & 63;
        Ws[dd][r] = W_dt[(size_t)(d0 + dd) * RK + r];
    }
    __syncthreads();
    const int ll = tid & 63;   // lane-contiguous l -> coalesced stores
    const int dg = tid >> 6;   // 0..3
    float acc[16];
    #pragma unroll
    for (int i = 0; i < 16; i++) acc[i] = 0.f;
    #pragma unroll 8
    for (int r = 0; r < 64; r++) {
        float v = dts[ll][r];
        #pragma unroll
        for (int i = 0; i < 16; i++) acc[i] = fmaf(Ws[dg + 4 * i][r], v, acc[i]);
    }
    #pragma unroll
    for (int i = 0; i < 16; i++) {
        int dd = dg + 4 * i;
        float z = acc[i] + b_dt[d0 + dd];
        g_deltaT[(size_t)(d0 + dd) * L_SEQ + l0 + ll] = softplus_f(z);
    }
}

// ---------------- selective scan ----------------
// warp = 2 channels x 16 states. lane<16 -> channel 2*bid, lane>=16 -> 2*bid+1.
__global__ void scan_kernel(const float* __restrict__ A_log, const float* __restrict__ Dp) {
    const int lane = threadIdx.x;           // 32 threads per block
    const int half = lane >> 4;
    const int n = lane & 15;
    const int d = blockIdx.x * 2 + half;

    const float Aval = -__expf(A_log[(size_t)d * NS + n]);
    const float Dval = Dp[d];

    const float* dp = g_deltaT + (size_t)d * L_SEQ;
    const float* xp = g_xsT + (size_t)d * L_SEQ;
    const float* gp = g_gT + (size_t)d * L_SEQ;
    __nv_bfloat162* op = (__nv_bfloat162*)(g_ygT + (size_t)d * L_SEQ);

    float h = 0.f;

    // prefetch iteration 0
    float4 dl = *(const float4*)dp;
    float4 xs = *(const float4*)xp;
    float4 gg = *(const float4*)gp;
    float bc0 = g_BC[0 * 32 + lane];
    float bc1 = g_BC[1 * 32 + lane];
    float bc2 = g_BC[2 * 32 + lane];
    float bc3 = g_BC[3 * 32 + lane];

    for (int l0 = 0; l0 < L_SEQ; l0 += 4) {
        float4 dlc = dl, xsc = xs, ggc = gg;
        float bcc[4] = {bc0, bc1, bc2, bc3};
        int ln = l0 + 4;
        if (ln < L_SEQ) {
            dl = *(const float4*)(dp + ln);
            xs = *(const float4*)(xp + ln);
            gg = *(const float4*)(gp + ln);
            bc0 = g_BC[(size_t)(ln + 0) * 32 + lane];
            bc1 = g_BC[(size_t)(ln + 1) * 32 + lane];
            bc2 = g_BC[(size_t)(ln + 2) * 32 + lane];
            bc3 = g_BC[(size_t)(ln + 3) * 32 + lane];
        }
        float y[4];
        #pragma unroll
        for (int j = 0; j < 4; j++) {
            float delta = f4_get(dlc, j);
            float xsv   = f4_get(xsc, j);
            float Bv = __shfl_sync(0xffffffffu, bcc[j], n);
            float Cv = __shfl_sync(0xffffffffu, bcc[j], n + 16);
            float dA = __expf(delta * Aval);
            h = fmaf(dA, h, delta * xsv * Bv);
            float p = h * Cv;
            p += __shfl_xor_sync(0xffffffffu, p, 1);
            p += __shfl_xor_sync(0xffffffffu, p, 2);
            p += __shfl_xor_sync(0xffffffffu, p, 4);
            p += __shfl_xor_sync(0xffffffffu, p, 8);
            y[j] = fmaf(xsv, Dval, p) * f4_get(ggc, j);
        }
        if (n == 0) {
            op[(l0 >> 1) + 0] = __floats2bfloat162_rn(y[0], y[1]);
            op[(l0 >> 1) + 1] = __floats2bfloat162_rn(y[2], y[3]);
        }
    }
}

// ---------------- residual add ----------------
__global__ void resadd_kernel(const float* __restrict__ x, float* __restrict__ out) {
    size_t i = (size_t)blockIdx.x * blockDim.x + threadIdx.x;  // over L*DM/4 float4
    float4 a = ((const float4*)x)[i];
    float4 b = ((float4*)out)[i];
    ((float4*)out)[i] = make_float4(a.x + b.x, a.y + b.y, a.z + b.z, a.w + b.w);
}

// ---------------- launch ----------------
extern "C" void kernel_launch(void* const* d_in, const int* in_sizes, int n_in,
                              void* d_out, int out_size) {
    const float* x      = (const float*)d_in[0];
    const float* W_in   = (const float*)d_in[1];
    const float* conv_w = (const float*)d_in[2];
    const float* conv_b = (const float*)d_in[3];
    const float* W_xprj = (const float*)d_in[4];
    const float* W_dt   = (const float*)d_in[5];
    const float* b_dt   = (const float*)d_in[6];
    const float* A_log  = (const float*)d_in[7];
    const float* Dp     = (const float*)d_in[8];
    const float* W_out  = (const float*)d_in[9];
    const float* norm_w = (const float*)d_in[10];
    float* out = (float*)d_out;

    // 1) weight conversions to bf16
    f2bf_kernel<<<512, 256>>>(W_in,   0, (2 * DI * DM) / 2);
    f2bf_kernel<<<96,  256>>>(W_xprj, 1, (NX * DI) / 2);
    f2bf_kernel<<<512, 256>>>(W_out,  2, (DM * DI) / 2);

    // 2) RMSNorm -> g_xn (bf16 [l][dm])
    rmsnorm_kernel<<<L_SEQ, 256>>>(x, norm_w);

    // 3) in_proj: g_xzT[e][l] = W_in @ xn^T   (M=4096, N=2048, K=1024)
    {
        const __nv_bfloat16* Ag; const __nv_bfloat16* Bg; float* Cg;
        cudaGetSymbolAddress((void**)&Ag, g_Win);
        cudaGetSymbolAddress((void**)&Bg, g_xn);
        cudaGetSymbolAddress((void**)&Cg, g_xzT);
        dim3 grid(L_SEQ / GBN, (2 * DI) / GBM);
        gemm_kernel<true><<<grid, 256>>>(Ag, Bg, Cg, 2 * DI, L_SEQ, DM);
    }

    // 4) depthwise conv + silu -> g_xsT / g_xsTb
    conv_kernel<<<DI, 256>>>(conv_w, conv_b);

    // 5) gate: silu(res) -> g_gT
    gate_kernel<<<(DI * L_SEQ / 4) / 256, 256>>>();

    // 6) x_proj: g_dbc[l][n] = xs @ W_xproj^T  (M=2048, N=96, K=2048)
    {
        const __nv_bfloat16* Ag; const __nv_bfloat16* Bg; float* Cg;
        cudaGetSymbolAddress((void**)&Ag, g_xsTb);
        cudaGetSymbolAddress((void**)&Bg, g_Wxp);
        cudaGetSymbolAddress((void**)&Cg, g_dbc);
        dim3 grid((NX + GBN - 1) / GBN, L_SEQ / GBM);
        gemm_kernel<false><<<grid, 256>>>(Ag, Bg, Cg, L_SEQ, NX, DI);
    }

    // 7) repack B/C time-major
    bc_repack_kernel<<<(L_SEQ * 32) / 256, 256>>>();

    // 8) delta projection + softplus -> g_deltaT [d][l]
    {
        dim3 grid(L_SEQ / 64, DI / 64);
        delta_kernel<<<grid, 256>>>(W_dt, b_dt);
    }

    // 9) selective scan (+D skip, +gating) -> g_ygT (bf16 [d][l])
    scan_kernel<<<DI / 2, 32>>>(A_log, Dp);

    // 10) out_proj: out[l][e] = yg @ W_out^T  (M=2048, N=1024, K=2048)
    {
        const __nv_bfloat16* Ag; const __nv_bfloat16* Bg;
        cudaGetSymbolAddress((void**)&Ag, g_ygT);
        cudaGetSymbolAddress((void**)&Bg, g_Wout);
        dim3 grid(DM / GBN, L_SEQ / GBM);
        gemm_kernel<false><<<grid, 256>>>(Ag, Bg, out, L_SEQ, DM, DI);
    }

    // 11) residual
    resadd_kernel<<<(L_SEQ * DM / 4) / 256, 256>>>(x, out);
}

// round 17
// speedup vs baseline: 1.7150x; 1.7150x over previous
#include <cuda_runtime.h>
#include <cuda_bf16.h>
#include <mma.h>
#include <cstdint>
#include <type_traits>

using namespace nvcuda;

// ---------------- problem constants ----------------
#define L_SEQ 2048
#define DM    1024
#define DI    2048
#define NX    96      // dt_rank + 2*d_state
#define RK    64      // dt_rank
#define NS    16      // d_state

// ---------------- device scratch (static globals, no allocs) ----------------
__device__ __align__(128) __nv_bfloat16 g_xn  [(size_t)L_SEQ * DM];     // normalized input  [l][dm]
__device__ __align__(128) __nv_bfloat16 g_Win [(size_t)2 * DI * DM];    // W_in bf16 [4096][1024]
__device__ __align__(128) __nv_bfloat16 g_Wxp [(size_t)NX * DI];        // W_xproj bf16 [96][2048]
__device__ __align__(128) __nv_bfloat16 g_Wout[(size_t)DM * DI];        // W_out bf16 [1024][2048]
__device__ __align__(128) float         g_xzT [(size_t)DI * L_SEQ];     // in_proj x-branch, [d][l]
__device__ __align__(128) float         g_xsT [(size_t)DI * L_SEQ];     // conv+silu fp32 [d][l]
__device__ __align__(128) __nv_bfloat16 g_xsTb[(size_t)DI * L_SEQ];     // conv+silu bf16 [d][l]
__device__ __align__(128) float         g_dbc [(size_t)L_SEQ * NX];     // x_proj out [l][96]
__device__ __align__(128) float         g_BC  [(size_t)L_SEQ * 32];     // [l][0..15]=B, [16..31]=C
__device__ __align__(128) float         g_deltaT[(size_t)DI * L_SEQ];   // softplus delta [d][l]
__device__ __align__(128) float         g_gT  [(size_t)DI * L_SEQ];     // silu(res) [d][l]
__device__ __align__(128) __nv_bfloat16 g_ygT [(size_t)DI * L_SEQ];     // gated scan out bf16 [d][l]

// ---------------- helpers ----------------
__device__ __forceinline__ float silu_f(float z) {
    return z / (1.f + __expf(-z));
}
__device__ __forceinline__ float softplus_f(float z) {
    return (z > 20.f) ? z : log1pf(__expf(z));
}
__device__ __forceinline__ float f4_get(const float4& v, int j) {
    switch (j) { case 0: return v.x; case 1: return v.y; case 2: return v.z; default: return v.w; }
}

// cp.async 16B with zero-fill predicate
__device__ __forceinline__ void cpa16(void* dst, const void* src, bool pred) {
    unsigned s = (unsigned)__cvta_generic_to_shared(dst);
    int sz = pred ? 16 : 0;
    asm volatile("cp.async.cg.shared.global [%0], [%1], 16, %2;\n" :: "r"(s), "l"(src), "r"(sz));
}
__device__ __forceinline__ void cpa_commit() { asm volatile("cp.async.commit_group;\n"); }
template<int W> __device__ __forceinline__ void cpa_wait() {
    asm volatile("cp.async.wait_group %0;\n" :: "n"(W));
}

// ---------------- fp32 -> bf16 weight conversion ----------------
__global__ void f2bf_kernel(const float* __restrict__ src, int which, int n2) {
    __nv_bfloat16* dst = (which == 0) ? g_Win : (which == 1) ? g_Wxp : g_Wout;
    int stride = gridDim.x * blockDim.x;
    for (int i = blockIdx.x * blockDim.x + threadIdx.x; i < n2; i += stride) {
        float2 v = ((const float2*)src)[i];
        ((__nv_bfloat162*)dst)[i] = __floats2bfloat162_rn(v.x, v.y);
    }
}

// ---------------- RMSNorm: x[l][1024] fp32 -> g_xn bf16 ----------------
__global__ void rmsnorm_kernel(const float* __restrict__ x, const float* __restrict__ nw) {
    const int l = blockIdx.x;
    const int tid = threadIdx.x;  // 256 threads x 4 elems
    float4 v = ((const float4*)(x + (size_t)l * DM))[tid];
    float ss = v.x * v.x + v.y * v.y + v.z * v.z + v.w * v.w;
    #pragma unroll
    for (int o = 16; o > 0; o >>= 1) ss += __shfl_xor_sync(0xffffffffu, ss, o);
    __shared__ float wsum[8];
    if ((tid & 31) == 0) wsum[tid >> 5] = ss;
    __syncthreads();
    float tot = 0.f;
    #pragma unroll
    for (int w = 0; w < 8; w++) tot += wsum[w];
    float r = rsqrtf(tot * (1.0f / DM) + 1e-5f);
    float4 w4 = ((const float4*)nw)[tid];
    __nv_bfloat162* op = (__nv_bfloat162*)(g_xn + (size_t)l * DM);
    op[tid * 2 + 0] = __floats2bfloat162_rn(v.x * r * w4.x, v.y * r * w4.y);
    op[tid * 2 + 1] = __floats2bfloat162_rn(v.z * r * w4.z, v.w * r * w4.w);
}

// ---------------- double-buffered cp.async bf16 wmma GEMM ----------------
// C[m,n] fp32 row-major ld=N = sum_k A(m,k)*B(k,n)
//   AKM=true :  A(m,k) = Ag[m*K + k]   (A row-major / K-major)
//   AKM=false:  A(m,k) = Ag[k*M + m]   (A col-major / M-major) -> col_major frag, NO scatter
//   B(k,n) = Bg[n*K + k]               (always; col_major frag, NO scatter)
// EPI: 0 = plain store
//      1 = in_proj split: blocks with m0<DI store to C (=g_xzT), blocks with
//          m0>=DI apply silu and store to G (=g_gT) at row (m-DI)
//      2 = residual: C[row] = acc + X[row]
// Requires: M%128==0, K%32==0, N%BN arbitrary (predicated), BN%(16*WNW)==0.
template<bool AKM, int BN, int WMW, int WNW, int EPI>
__global__ __launch_bounds__(256)
void gemm_db(const __nv_bfloat16* __restrict__ Ag,
             const __nv_bfloat16* __restrict__ Bg,
             float* __restrict__ C,
             const float* __restrict__ X,
             float* __restrict__ G,
             int M, int N, int K) {
    constexpr int BM = 128, BK = 32;
    constexpr int A_ROWS = AKM ? BM : BK;
    constexpr int A_LD   = AKM ? (BK + 8) : (BM + 8);
    constexpr int B_LD   = BK + 8;
    constexpr int FR = (BM / WMW) / 16;
    constexpr int FC = (BN / WNW) / 16;
    using ALayout = typename std::conditional<AKM, wmma::row_major, wmma::col_major>::type;

    __shared__ __align__(16) __nv_bfloat16 As[2][A_ROWS][A_LD];
    __shared__ __align__(16) __nv_bfloat16 Bs[2][BN][B_LD];

    const int tid = threadIdx.x;           // 256
    const int warpId = tid >> 5;
    const int wr = warpId % WMW;
    const int wc = warpId / WMW;
    const int m0 = blockIdx.y * BM;
    const int n0 = blockIdx.x * BN;
    const int mBase = wr * (BM / WMW);
    const int nBase = wc * (BN / WNW);

    wmma::fragment<wmma::accumulator, 16, 16, 16, float> acc[FR][FC];
    #pragma unroll
    for (int i = 0; i < FR; i++)
        #pragma unroll
        for (int j = 0; j < FC; j++)
            wmma::fill_fragment(acc[i][j], 0.0f);

    auto load_tiles = [&](int kt, int buf) {
        const int k0 = kt * BK;
        if constexpr (AKM) {
            #pragma unroll
            for (int c = tid; c < BM * BK / 8; c += 256) {
                int mm = c >> 2, kq = c & 3;   // 4 x 16B per 32-wide row
                cpa16(&As[buf][mm][kq * 8],
                      Ag + (size_t)(m0 + mm) * K + k0 + kq * 8, true);
            }
        } else {
            #pragma unroll
            for (int c = tid; c < BK * BM / 8; c += 256) {
                int kk = c >> 4, mq = c & 15;  // 16 x 16B per 128-wide row
                cpa16(&As[buf][kk][mq * 8],
                      Ag + (size_t)(k0 + kk) * M + m0 + mq * 8, true);
            }
        }
        #pragma unroll
        for (int c = tid; c < BN * BK / 8; c += 256) {
            int nn = c >> 2, kq = c & 3;
            bool p = (n0 + nn) < N;
            const __nv_bfloat16* src = Bg + (size_t)(p ? (n0 + nn) : 0) * K + k0 + kq * 8;
            cpa16(&Bs[buf][nn][kq * 8], src, p);
        }
    };

    const int KT = K / BK;
    load_tiles(0, 0);
    cpa_commit();

    for (int kt = 0; kt < KT; kt++) {
        const int buf = kt & 1;
        if (kt + 1 < KT) {
            load_tiles(kt + 1, buf ^ 1);
            cpa_commit();
            cpa_wait<1>();
        } else {
            cpa_wait<0>();
        }
        __syncthreads();

        #pragma unroll
        for (int kk = 0; kk < BK; kk += 16) {
            wmma::fragment<wmma::matrix_a, 16, 16, 16, __nv_bfloat16, ALayout> af[FR];
            wmma::fragment<wmma::matrix_b, 16, 16, 16, __nv_bfloat16, wmma::col_major> bf[FC];
            #pragma unroll
            for (int i = 0; i < FR; i++) {
                if constexpr (AKM)
                    wmma::load_matrix_sync(af[i], &As[buf][mBase + i * 16][kk], A_LD);
                else
                    wmma::load_matrix_sync(af[i], &As[buf][kk][mBase + i * 16], A_LD);
            }
            #pragma unroll
            for (int j = 0; j < FC; j++)
                wmma::load_matrix_sync(bf[j], &Bs[buf][nBase + j * 16][kk], B_LD);
            #pragma unroll
            for (int i = 0; i < FR; i++)
                #pragma unroll
                for (int j = 0; j < FC; j++)
                    wmma::mma_sync(acc[i][j], af[i], bf[j], acc[i][j]);
        }
        __syncthreads();
    }

    // ---- epilogue ----
    #pragma unroll
    for (int i = 0; i < FR; i++) {
        #pragma unroll
        for (int j = 0; j < FC; j++) {
            const int row = m0 + mBase + i * 16;
            const int col = n0 + nBase + j * 16;
            if (col >= N) continue;
            if constexpr (EPI == 0) {
                wmma::store_matrix_sync(&C[(size_t)row * N + col], acc[i][j], N,
                                        wmma::mem_row_major);
            } else if constexpr (EPI == 1) {
                if (m0 >= DI) {  // whole 128-row block is the gate branch
                    #pragma unroll
                    for (int t = 0; t < acc[i][j].num_elements; t++)
                        acc[i][j].x[t] = silu_f(acc[i][j].x[t]);
                    wmma::store_matrix_sync(&G[(size_t)(row - DI) * N + col], acc[i][j], N,
                                            wmma::mem_row_major);
                } else {
                    wmma::store_matrix_sync(&C[(size_t)row * N + col], acc[i][j], N,
                                            wmma::mem_row_major);
                }
            } else {  // EPI == 2: fused residual add
                wmma::fragment<wmma::accumulator, 16, 16, 16, float> xf;
                wmma::load_matrix_sync(xf, &X[(size_t)row * N + col], N, wmma::mem_row_major);
                #pragma unroll
                for (int t = 0; t < acc[i][j].num_elements; t++)
                    acc[i][j].x[t] += xf.x[t];
                wmma::store_matrix_sync(&C[(size_t)row * N + col], acc[i][j], N,
                                        wmma::mem_row_major);
            }
        }
    }
}

// ---------------- depthwise causal conv1d + silu ----------------
__global__ void conv_kernel(const float* __restrict__ conv_w, const float* __restrict__ conv_b) {
    const int d = blockIdx.x;
    __shared__ float row[L_SEQ + 4];
    const int tid = threadIdx.x;  // 256
    if (tid < 4) row[tid] = 0.f;
    const float* src = g_xzT + (size_t)d * L_SEQ;
    float4* dst4 = (float4*)(row + 4);
    for (int i = tid; i < L_SEQ / 4; i += 256) dst4[i] = ((const float4*)src)[i];
    __syncthreads();
    const float w0 = conv_w[d * 4 + 0], w1 = conv_w[d * 4 + 1];
    const float w2 = conv_w[d * 4 + 2], w3 = conv_w[d * 4 + 3];
    const float b = conv_b[d];
    float* outF = g_xsT + (size_t)d * L_SEQ;
    __nv_bfloat162* outB = (__nv_bfloat162*)(g_xsTb + (size_t)d * L_SEQ);
    for (int i = tid; i < L_SEQ / 4; i += 256) {
        int l = i * 4;
        float o[4];
        #pragma unroll
        for (int j = 0; j < 4; j++) {
            int ll = l + j;
            float s = row[ll + 1] * w0 + row[ll + 2] * w1 + row[ll + 3] * w2 + row[ll + 4] * w3 + b;
            o[j] = silu_f(s);
        }
        ((float4*)outF)[i] = make_float4(o[0], o[1], o[2], o[3]);
        outB[i * 2 + 0] = __floats2bfloat162_rn(o[0], o[1]);
        outB[i * 2 + 1] = __floats2bfloat162_rn(o[2], o[3]);
    }
}

// ---------------- BC repack: [l][96] cols 64..95 -> [l][32] ----------------
__global__ void bc_repack_kernel() {
    int idx = blockIdx.x * blockDim.x + threadIdx.x;  // L*32
    int l = idx >> 5, j = idx & 31;
    g_BC[idx] = g_dbc[(size_t)l * NX + RK + j];
}

// ---------------- delta projection + softplus ----------------
// deltaT[d][l] = softplus(b_dt[d] + sum_r W_dt[d][r] * dbc[l][r])
__global__ void delta_kernel(const float* __restrict__ W_dt, const float* __restrict__ b_dt) {
    __shared__ float dts[64][65];
    __shared__ float Ws [64][65];
    const int l0 = blockIdx.x * 64;
    const int d0 = blockIdx.y * 64;
    const int tid = threadIdx.x;  // 256
    for (int i = tid; i < 64 * 64; i += 256) {
        int ll = i >> 6, r = i & 63;
        dts[ll][r] = g_dbc[(size_t)(l0 + ll) * NX + r];
    }
    for (int i = tid; i < 64 * 64; i += 256) {
        int dd = i >> 6, r = i & 63;
        Ws[dd][r] = W_dt[(size_t)(d0 + dd) * RK + r];
    }
    __syncthreads();
    const int ll = tid & 63;   // lane-contiguous l -> coalesced stores
    const int dg = tid >> 6;   // 0..3
    float acc[16];
    #pragma unroll
    for (int i = 0; i < 16; i++) acc[i] = 0.f;
    #pragma unroll 8
    for (int r = 0; r < 64; r++) {
        float v = dts[ll][r];
        #pragma unroll
        for (int i = 0; i < 16; i++) acc[i] = fmaf(Ws[dg + 4 * i][r], v, acc[i]);
    }
    #pragma unroll
    for (int i = 0; i < 16; i++) {
        int dd = dg + 4 * i;
        float z = acc[i] + b_dt[d0 + dd];
        g_deltaT[(size_t)(d0 + dd) * L_SEQ + l0 + ll] = softplus_f(z);
    }
}

// ---------------- selective scan ----------------
// warp = 2 channels x 16 states. lane<16 -> channel 2*bid, lane>=16 -> 2*bid+1.
__global__ void scan_kernel(const float* __restrict__ A_log, const float* __restrict__ Dp) {
    const int lane = threadIdx.x;           // 32 threads per block
    const int half = lane >> 4;
    const int n = lane & 15;
    const int d = blockIdx.x * 2 + half;

    const float Aval = -__expf(A_log[(size_t)d * NS + n]);
    const float Dval = Dp[d];

    const float* dp = g_deltaT + (size_t)d * L_SEQ;
    const float* xp = g_xsT + (size_t)d * L_SEQ;
    const float* gp = g_gT + (size_t)d * L_SEQ;
    __nv_bfloat162* op = (__nv_bfloat162*)(g_ygT + (size_t)d * L_SEQ);

    float h = 0.f;

    // prefetch iteration 0
    float4 dl = *(const float4*)dp;
    float4 xs = *(const float4*)xp;
    float4 gg = *(const float4*)gp;
    float bc0 = g_BC[0 * 32 + lane];
    float bc1 = g_BC[1 * 32 + lane];
    float bc2 = g_BC[2 * 32 + lane];
    float bc3 = g_BC[3 * 32 + lane];

    for (int l0 = 0; l0 < L_SEQ; l0 += 4) {
        float4 dlc = dl, xsc = xs, ggc = gg;
        float bcc[4] = {bc0, bc1, bc2, bc3};
        int ln = l0 + 4;
        if (ln < L_SEQ) {
            dl = *(const float4*)(dp + ln);
            xs = *(const float4*)(xp + ln);
            gg = *(const float4*)(gp + ln);
            bc0 = g_BC[(size_t)(ln + 0) * 32 + lane];
            bc1 = g_BC[(size_t)(ln + 1) * 32 + lane];
            bc2 = g_BC[(size_t)(ln + 2) * 32 + lane];
            bc3 = g_BC[(size_t)(ln + 3) * 32 + lane];
        }
        float y[4];
        #pragma unroll
        for (int j = 0; j < 4; j++) {
            float delta = f4_get(dlc, j);
            float xsv   = f4_get(xsc, j);
            float Bv = __shfl_sync(0xffffffffu, bcc[j], n);
            float Cv = __shfl_sync(0xffffffffu, bcc[j], n + 16);
            float dA = __expf(delta * Aval);
            h = fmaf(dA, h, delta * xsv * Bv);
            float p = h * Cv;
            p += __shfl_xor_sync(0xffffffffu, p, 1);
            p += __shfl_xor_sync(0xffffffffu, p, 2);
            p += __shfl_xor_sync(0xffffffffu, p, 4);
            p += __shfl_xor_sync(0xffffffffu, p, 8);
            y[j] = fmaf(xsv, Dval, p) * f4_get(ggc, j);
        }
        if (n == 0) {
            op[(l0 >> 1) + 0] = __floats2bfloat162_rn(y[0], y[1]);
            op[(l0 >> 1) + 1] = __floats2bfloat162_rn(y[2], y[3]);
        }
    }
}

// ---------------- launch ----------------
extern "C" void kernel_launch(void* const* d_in, const int* in_sizes, int n_in,
                              void* d_out, int out_size) {
    const float* x      = (const float*)d_in[0];
    const float* W_in   = (const float*)d_in[1];
    const float* conv_w = (const float*)d_in[2];
    const float* conv_b = (const float*)d_in[3];
    const float* W_xprj = (const float*)d_in[4];
    const float* W_dt   = (const float*)d_in[5];
    const float* b_dt   = (const float*)d_in[6];
    const float* A_log  = (const float*)d_in[7];
    const float* Dp     = (const float*)d_in[8];
    const float* W_out  = (const float*)d_in[9];
    const float* norm_w = (const float*)d_in[10];
    float* out = (float*)d_out;

    __nv_bfloat16 *pWin, *pWxp, *pWout, *pXn, *pXsTb, *pYgT;
    float *pXzT, *pGt, *pDbc;
    cudaGetSymbolAddress((void**)&pWin,  g_Win);
    cudaGetSymbolAddress((void**)&pWxp,  g_Wxp);
    cudaGetSymbolAddress((void**)&pWout, g_Wout);
    cudaGetSymbolAddress((void**)&pXn,   g_xn);
    cudaGetSymbolAddress((void**)&pXsTb, g_xsTb);
    cudaGetSymbolAddress((void**)&pYgT,  g_ygT);
    cudaGetSymbolAddress((void**)&pXzT,  g_xzT);
    cudaGetSymbolAddress((void**)&pGt,   g_gT);
    cudaGetSymbolAddress((void**)&pDbc,  g_dbc);

    // 1) weight conversions to bf16
    f2bf_kernel<<<512, 256>>>(W_in,   0, (2 * DI * DM) / 2);
    f2bf_kernel<<<96,  256>>>(W_xprj, 1, (NX * DI) / 2);
    f2bf_kernel<<<512, 256>>>(W_out,  2, (DM * DI) / 2);

    // 2) RMSNorm -> g_xn (bf16 [l][dm])
    rmsnorm_kernel<<<L_SEQ, 256>>>(x, norm_w);

    // 3) in_proj: x-branch -> g_xzT [d][l]; gate branch -> silu -> g_gT [d][l]
    //    M=4096, N=2048, K=1024; A=W_in K-major, B=g_xn
    {
        dim3 grid(L_SEQ / 128, (2 * DI) / 128);
        gemm_db<true, 128, 2, 4, 1><<<grid, 256>>>(pWin, pXn, pXzT, nullptr, pGt,
                                                   2 * DI, L_SEQ, DM);
    }

    // 4) depthwise conv + silu -> g_xsT / g_xsTb
    conv_kernel<<<DI, 256>>>(conv_w, conv_b);

    // 5) x_proj: g_dbc[l][n] = xs @ W_xproj^T  (M=2048, N=96, K=2048), A M-major
    {
        dim3 grid(NX / 32, L_SEQ / 128);
        gemm_db<false, 32, 8, 1, 0><<<grid, 256>>>(pXsTb, pWxp, pDbc, nullptr, nullptr,
                                                   L_SEQ, NX, DI);
    }

    // 6) repack B/C time-major
    bc_repack_kernel<<<(L_SEQ * 32) / 256, 256>>>();

    // 7) delta projection + softplus -> g_deltaT [d][l]
    {
        dim3 grid(L_SEQ / 64, DI / 64);
        delta_kernel<<<grid, 256>>>(W_dt, b_dt);
    }

    // 8) selective scan (+D skip, +gating) -> g_ygT (bf16 [d][l])
    scan_kernel<<<DI / 2, 32>>>(A_log, Dp);

    // 9) out_proj + residual: out[l][e] = yg @ W_out^T + x  (M=2048, N=1024, K=2048)
    {
        dim3 grid(DM / 128, L_SEQ / 128);
        gemm_db<false, 128, 2, 4, 2><<<grid, 256>>>(pYgT, pWout, out, x, nullptr,
                                                    L_SEQ, DM, DI);
    }
}